// round 1
// baseline (speedup 1.0000x reference)
#include <cuda_runtime.h>
#include <cuda_bf16.h>
#include <math.h>

// Problem constants
#define BB 4
#define SS 1024
#define DD 1024
#define HH 16
#define DHH 64
#define FFN 4096
#define ROWS (BB*SS)   // 4096

// ---------------- scratch (device globals: the sanctioned scratch path) ----
__device__ float g_h  [ROWS*DD];     // layernorm output (reused for LN1 & LN2)
__device__ float g_q  [ROWS*DD];     // (B,H,S,DH)
__device__ float g_k  [ROWS*DD];
__device__ float g_v  [ROWS*DD];
__device__ float g_ao [ROWS*DD];     // attention output, (B,S,D)
__device__ float g_o1 [ROWS*DD];     // attn proj + residual
__device__ float g_mid[ROWS*FFN];    // FFN hidden

// ---------------- LayerNorm: one block per row --------------------------
__global__ void layernorm_k(const float* __restrict__ x, const float* __restrict__ g,
                            const float* __restrict__ b, float* __restrict__ out)
{
    __shared__ float red0[8], red1[8];
    int row = blockIdx.x, tid = threadIdx.x;
    const float4* xr = (const float4*)(x + (size_t)row * DD);
    float4 v = xr[tid];
    float s  = v.x + v.y + v.z + v.w;
    float s2 = v.x*v.x + v.y*v.y + v.z*v.z + v.w*v.w;
    #pragma unroll
    for (int o = 16; o; o >>= 1) {
        s  += __shfl_xor_sync(0xffffffffu, s,  o);
        s2 += __shfl_xor_sync(0xffffffffu, s2, o);
    }
    if ((tid & 31) == 0) { red0[tid >> 5] = s; red1[tid >> 5] = s2; }
    __syncthreads();
    float S = 0.f, S2 = 0.f;
    #pragma unroll
    for (int i = 0; i < 8; i++) { S += red0[i]; S2 += red1[i]; }
    float mean = S * (1.f / DD);
    float var  = S2 * (1.f / DD) - mean * mean;
    float rstd = rsqrtf(var + 1e-5f);
    float4 gv = ((const float4*)g)[tid];
    float4 bv = ((const float4*)b)[tid];
    float4 o;
    o.x = (v.x - mean) * rstd * gv.x + bv.x;
    o.y = (v.y - mean) * rstd * gv.y + bv.y;
    o.z = (v.z - mean) * rstd * gv.z + bv.z;
    o.w = (v.w - mean) * rstd * gv.w + bv.w;
    ((float4*)(out + (size_t)row * DD))[tid] = o;
}

// ---------------- GEMM: C[M,N] = A[M,K] @ W[K,N] + bias, fused epilogues --
// EPI 0: plain+bias, 1: bias + store to (B,H,S,DH), 2: bias+residual, 3: bias+GELU
template<int EPI>
__global__ void __launch_bounds__(256, 2)
gemm128(const float* __restrict__ A, const float* __restrict__ W,
        const float* __restrict__ bias, const float* __restrict__ res,
        float* __restrict__ C, int M, int N, int K)
{
    __shared__ float As[16][128];
    __shared__ float Bs[16][128];
    int tid = threadIdx.x;
    int tx = tid & 15, ty = tid >> 4;
    int m0 = blockIdx.y * 128, n0 = blockIdx.x * 128;
    float acc[8][8] = {};
    const float* Ab = A + (size_t)m0 * K;
    const float* Wb = W + n0;

    for (int k0 = 0; k0 < K; k0 += 16) {
        #pragma unroll
        for (int i = 0; i < 2; i++) {
            int vnum = tid + i * 256;
            int row = vnum >> 2, c4 = (vnum & 3) * 4;
            float4 a = *(const float4*)(Ab + (size_t)row * K + k0 + c4);
            As[c4 + 0][row] = a.x; As[c4 + 1][row] = a.y;
            As[c4 + 2][row] = a.z; As[c4 + 3][row] = a.w;
        }
        #pragma unroll
        for (int i = 0; i < 2; i++) {
            int vnum = tid + i * 256;
            int row = vnum >> 5, c4 = (vnum & 31) * 4;
            *(float4*)&Bs[row][c4] = *(const float4*)(Wb + (size_t)(k0 + row) * N + c4);
        }
        __syncthreads();
        #pragma unroll
        for (int kk = 0; kk < 16; kk++) {
            float a[8], b[8];
            *(float4*)(a)     = *(float4*)&As[kk][ty * 8];
            *(float4*)(a + 4) = *(float4*)&As[kk][ty * 8 + 4];
            *(float4*)(b)     = *(float4*)&Bs[kk][tx * 8];
            *(float4*)(b + 4) = *(float4*)&Bs[kk][tx * 8 + 4];
            #pragma unroll
            for (int i = 0; i < 8; i++)
                #pragma unroll
                for (int j = 0; j < 8; j++)
                    acc[i][j] += a[i] * b[j];
        }
        __syncthreads();
    }

    #pragma unroll
    for (int i = 0; i < 8; i++) {
        int r = m0 + ty * 8 + i;
        #pragma unroll
        for (int j = 0; j < 8; j++) {
            int n = n0 + tx * 8 + j;
            float v = acc[i][j] + bias[n];
            if (EPI == 2) v += res[(size_t)r * N + n];
            if (EPI == 3) v = 0.5f * v * (1.0f + erff(v * 0.70710678118654752f));
            if (EPI == 1) {
                int bb = r >> 10, s = r & 1023, h = n >> 6, dh = n & 63;
                C[(((size_t)bb * HH + h) * SS + s) * DHH + dh] = v;
            } else {
                C[(size_t)r * N + n] = v;
            }
        }
    }
}

// ---------------- Flash attention: BQ=64, BK=64, DH=64 -------------------
// grid: (S/64, B*H); 256 threads = 16x16, each thread 4x4 microtile.
__global__ void __launch_bounds__(256)
flash_attn(const float* __restrict__ Q, const float* __restrict__ K,
           const float* __restrict__ V, float* __restrict__ O)
{
    extern __shared__ float sm[];
    const int LD = 65;
    float* Qs = sm;                 // 64*LD
    float* Ks = Qs + 64 * LD;
    float* Vs = Ks + 64 * LD;
    float* Ps = Vs + 64 * LD;
    float* m_sh = Ps + 64 * LD;     // 64
    float* l_sh = m_sh + 64;        // 64

    int tid = threadIdx.x;
    int tx = tid & 15, ty = tid >> 4;
    int bh = blockIdx.y;
    int q0 = blockIdx.x * 64;
    const float scale = 1.0f / 32.0f;  // 1/sqrt(D=1024)

    const float* Qb = Q + ((size_t)bh * SS + q0) * DHH;
    const float* Kb = K + (size_t)bh * SS * DHH;
    const float* Vb = V + (size_t)bh * SS * DHH;

    for (int i = tid; i < 64 * 64; i += 256) {
        int r = i >> 6, d = i & 63;
        Qs[r * LD + d] = Qb[(size_t)r * DHH + d] * scale;
    }
    int r0 = ty * 4, c0 = tx * 4;
    if (tx == 0) {
        #pragma unroll
        for (int i = 0; i < 4; i++) { m_sh[r0 + i] = -1e30f; l_sh[r0 + i] = 0.f; }
    }
    float acc[4][4] = {};
    __syncthreads();

    for (int t = 0; t < SS / 64; t++) {
        const float* Kt = Kb + (size_t)t * 64 * DHH;
        const float* Vt = Vb + (size_t)t * 64 * DHH;
        for (int i = tid; i < 64 * 64; i += 256) {
            int r = i >> 6, d = i & 63;
            Ks[r * LD + d] = Kt[i];
            Vs[r * LD + d] = Vt[i];
        }
        __syncthreads();

        float s[4][4] = {};
        #pragma unroll
        for (int d = 0; d < 64; d++) {
            float qv[4], kv[4];
            #pragma unroll
            for (int i = 0; i < 4; i++) qv[i] = Qs[(r0 + i) * LD + d];
            #pragma unroll
            for (int j = 0; j < 4; j++) kv[j] = Ks[(c0 + j) * LD + d];
            #pragma unroll
            for (int i = 0; i < 4; i++)
                #pragma unroll
                for (int j = 0; j < 4; j++)
                    s[i][j] += qv[i] * kv[j];
        }

        float rm[4], m_new[4], alpha[4], rs[4];
        #pragma unroll
        for (int i = 0; i < 4; i++) {
            rm[i] = fmaxf(fmaxf(s[i][0], s[i][1]), fmaxf(s[i][2], s[i][3]));
        }
        #pragma unroll
        for (int o = 1; o < 16; o <<= 1) {
            #pragma unroll
            for (int i = 0; i < 4; i++)
                rm[i] = fmaxf(rm[i], __shfl_xor_sync(0xffffffffu, rm[i], o));
        }
        #pragma unroll
        for (int i = 0; i < 4; i++) {
            float mo = m_sh[r0 + i];
            m_new[i] = fmaxf(mo, rm[i]);
            alpha[i] = __expf(mo - m_new[i]);
            rs[i] = 0.f;
            #pragma unroll
            for (int j = 0; j < 4; j++) {
                float p = __expf(s[i][j] - m_new[i]);
                s[i][j] = p;
                rs[i] += p;
            }
        }
        #pragma unroll
        for (int o = 1; o < 16; o <<= 1) {
            #pragma unroll
            for (int i = 0; i < 4; i++)
                rs[i] += __shfl_xor_sync(0xffffffffu, rs[i], o);
        }
        #pragma unroll
        for (int i = 0; i < 4; i++)
            #pragma unroll
            for (int j = 0; j < 4; j++)
                acc[i][j] *= alpha[i];
        __syncwarp();  // all lanes finished reading m_sh/l_sh before lane tx==0 writes
        if (tx == 0) {
            #pragma unroll
            for (int i = 0; i < 4; i++) {
                l_sh[r0 + i] = l_sh[r0 + i] * alpha[i] + rs[i];
                m_sh[r0 + i] = m_new[i];
            }
        }
        #pragma unroll
        for (int i = 0; i < 4; i++)
            #pragma unroll
            for (int j = 0; j < 4; j++)
                Ps[(r0 + i) * LD + c0 + j] = s[i][j];
        __syncthreads();

        #pragma unroll
        for (int k = 0; k < 64; k++) {
            float pv[4], vv[4];
            #pragma unroll
            for (int i = 0; i < 4; i++) pv[i] = Ps[(r0 + i) * LD + k];
            #pragma unroll
            for (int j = 0; j < 4; j++) vv[j] = Vs[k * LD + c0 + j];
            #pragma unroll
            for (int i = 0; i < 4; i++)
                #pragma unroll
                for (int j = 0; j < 4; j++)
                    acc[i][j] += pv[i] * vv[j];
        }
        __syncthreads();
    }

    int bb = bh >> 4, h = bh & 15;
    #pragma unroll
    for (int i = 0; i < 4; i++) {
        float inv = 1.0f / l_sh[r0 + i];
        int srow = q0 + r0 + i;
        #pragma unroll
        for (int j = 0; j < 4; j++) {
            O[((size_t)bb * SS + srow) * DD + h * DHH + c0 + j] = acc[i][j] * inv;
        }
    }
}

// ---------------- launch -------------------------------------------------
extern "C" void kernel_launch(void* const* d_in, const int* in_sizes, int n_in,
                              void* d_out, int out_size)
{
    const float* x    = (const float*)d_in[0];
    const float* wq   = (const float*)d_in[1];
    const float* bq   = (const float*)d_in[2];
    const float* wk   = (const float*)d_in[3];
    const float* bk   = (const float*)d_in[4];
    const float* wv   = (const float*)d_in[5];
    const float* bv   = (const float*)d_in[6];
    const float* wo   = (const float*)d_in[7];
    const float* bo   = (const float*)d_in[8];
    const float* g1   = (const float*)d_in[9];
    const float* b1   = (const float*)d_in[10];
    const float* g2   = (const float*)d_in[11];
    const float* b2   = (const float*)d_in[12];
    const float* wfc1 = (const float*)d_in[13];
    const float* bfc1 = (const float*)d_in[14];
    const float* wfc2 = (const float*)d_in[15];
    const float* bfc2 = (const float*)d_in[16];
    float* out = (float*)d_out;

    float *h, *q, *k, *v, *ao, *o1, *mid;
    cudaGetSymbolAddress((void**)&h,   g_h);
    cudaGetSymbolAddress((void**)&q,   g_q);
    cudaGetSymbolAddress((void**)&k,   g_k);
    cudaGetSymbolAddress((void**)&v,   g_v);
    cudaGetSymbolAddress((void**)&ao,  g_ao);
    cudaGetSymbolAddress((void**)&o1,  g_o1);
    cudaGetSymbolAddress((void**)&mid, g_mid);

    const int FLASH_SMEM = (4 * 64 * 65 + 128) * (int)sizeof(float); // 67072 B
    cudaFuncSetAttribute(flash_attn, cudaFuncAttributeMaxDynamicSharedMemorySize, FLASH_SMEM);

    // 1. LN1
    layernorm_k<<<ROWS, 256>>>(x, g1, b1, h);

    // 2. QKV projections (store to (B,H,S,DH))
    dim3 gQKV(DD / 128, ROWS / 128);
    gemm128<1><<<gQKV, 256>>>(h, wq, bq, nullptr, q, ROWS, DD, DD);
    gemm128<1><<<gQKV, 256>>>(h, wk, bk, nullptr, k, ROWS, DD, DD);
    gemm128<1><<<gQKV, 256>>>(h, wv, bv, nullptr, v, ROWS, DD, DD);

    // 3. flash attention
    flash_attn<<<dim3(SS / 64, BB * HH), 256, FLASH_SMEM>>>(q, k, v, ao);

    // 4. output projection + residual(x)
    gemm128<2><<<gQKV, 256>>>(ao, wo, bo, x, o1, ROWS, DD, DD);

    // 5. LN2
    layernorm_k<<<ROWS, 256>>>(o1, g2, b2, h);

    // 6. FC1 + GELU
    dim3 gFC1(FFN / 128, ROWS / 128);
    gemm128<3><<<gFC1, 256>>>(h, wfc1, bfc1, nullptr, mid, ROWS, FFN, DD);

    // 7. FC2 + residual(o1) -> out
    dim3 gFC2(DD / 128, ROWS / 128);
    gemm128<2><<<gFC2, 256>>>(mid, wfc2, bfc2, o1, out, ROWS, DD, FFN);
}

// round 3
// speedup vs baseline: 1.9501x; 1.9501x over previous
#include <cuda_runtime.h>
#include <cuda_bf16.h>
#include <math.h>
#include <stdint.h>

// ---------------- problem constants ----------------
#define BB 4
#define SS 1024
#define DD 1024
#define HH 16
#define DHH 64
#define FFN 4096
#define ROWS (BB*SS)   // 4096

// ---------------- device scratch ----------------
__device__ float g_q  [ROWS*DD];
__device__ float g_k  [ROWS*DD];
__device__ float g_v  [ROWS*DD];
__device__ float g_o1 [ROWS*DD];
// activation bf16 hi/lo (LN out, attn out reuse; FFN mid separate)
__device__ __nv_bfloat16 g_xh[ROWS*DD];
__device__ __nv_bfloat16 g_xl[ROWS*DD];
__device__ __nv_bfloat16 g_mh[(size_t)ROWS*FFN];
__device__ __nv_bfloat16 g_ml[(size_t)ROWS*FFN];
// transposed bf16 weights: [0]=hi, [1]=lo, layout [N,K] K-major
__device__ __nv_bfloat16 g_wqt[2][DD*DD];
__device__ __nv_bfloat16 g_wkt[2][DD*DD];
__device__ __nv_bfloat16 g_wvt[2][DD*DD];
__device__ __nv_bfloat16 g_wot[2][DD*DD];
__device__ __nv_bfloat16 g_w1t[2][(size_t)DD*FFN];
__device__ __nv_bfloat16 g_w2t[2][(size_t)DD*FFN];

// ---------------- small helpers ----------------
__device__ __forceinline__ uint32_t smem_u32(const void* p) {
    uint32_t a;
    asm("{ .reg .u64 t; cvta.to.shared.u64 t, %1; cvt.u32.u64 %0, t; }" : "=r"(a) : "l"(p));
    return a;
}
__device__ __forceinline__ void cp_async16(uint32_t s, const void* g) {
    asm volatile("cp.async.cg.shared.global [%0], [%1], 16;" :: "r"(s), "l"(g));
}
__device__ __forceinline__ void ldsm_x4(uint32_t* r, uint32_t addr) {
    asm volatile("ldmatrix.sync.aligned.m8n8.x4.shared.b16 {%0,%1,%2,%3}, [%4];"
        : "=r"(r[0]), "=r"(r[1]), "=r"(r[2]), "=r"(r[3]) : "r"(addr));
}
__device__ __forceinline__ void mma16816(float* d, const uint32_t* a, const uint32_t* b) {
    asm volatile("mma.sync.aligned.m16n8k16.row.col.f32.bf16.bf16.f32 "
        "{%0,%1,%2,%3}, {%4,%5,%6,%7}, {%8,%9}, {%0,%1,%2,%3};"
        : "+f"(d[0]), "+f"(d[1]), "+f"(d[2]), "+f"(d[3])
        : "r"(a[0]), "r"(a[1]), "r"(a[2]), "r"(a[3]), "r"(b[0]), "r"(b[1]));
}
__device__ __forceinline__ void split_bf16(float v, __nv_bfloat16& h, __nv_bfloat16& l) {
    h = __float2bfloat16_rn(v);
    l = __float2bfloat16_rn(v - __bfloat162float(h));
}

// ---------------- weight convert + transpose: W[K,N] fp32 -> Wt[N,K] bf16 hi/lo ----
__global__ void wconv(const float* __restrict__ W, __nv_bfloat16* __restrict__ Th,
                      __nv_bfloat16* __restrict__ Tl, int K, int N)
{
    __shared__ float tile[32][33];
    int tx = threadIdx.x, ty = threadIdx.y;      // 32 x 8
    int n0 = blockIdx.x * 32, k0 = blockIdx.y * 32;
    #pragma unroll
    for (int i = 0; i < 4; i++)
        tile[ty + i*8][tx] = W[(size_t)(k0 + ty + i*8) * N + n0 + tx];
    __syncthreads();
    #pragma unroll
    for (int i = 0; i < 4; i++) {
        int n = n0 + ty + i*8;
        int k = k0 + tx;
        float v = tile[tx][ty + i*8];
        __nv_bfloat16 h, l; split_bf16(v, h, l);
        Th[(size_t)n * K + k] = h;
        Tl[(size_t)n * K + k] = l;
    }
}

// ---------------- LayerNorm -> bf16 hi/lo ----------------
__global__ void layernorm_bf(const float* __restrict__ x, const float* __restrict__ g,
                             const float* __restrict__ b,
                             __nv_bfloat16* __restrict__ oh, __nv_bfloat16* __restrict__ ol)
{
    __shared__ float red0[8], red1[8];
    int row = blockIdx.x, tid = threadIdx.x;
    const float4* xr = (const float4*)(x + (size_t)row * DD);
    float4 v = xr[tid];
    float s  = v.x + v.y + v.z + v.w;
    float s2 = v.x*v.x + v.y*v.y + v.z*v.z + v.w*v.w;
    #pragma unroll
    for (int o = 16; o; o >>= 1) {
        s  += __shfl_xor_sync(0xffffffffu, s,  o);
        s2 += __shfl_xor_sync(0xffffffffu, s2, o);
    }
    if ((tid & 31) == 0) { red0[tid >> 5] = s; red1[tid >> 5] = s2; }
    __syncthreads();
    float S = 0.f, S2 = 0.f;
    #pragma unroll
    for (int i = 0; i < 8; i++) { S += red0[i]; S2 += red1[i]; }
    float mean = S * (1.f / DD);
    float var  = S2 * (1.f / DD) - mean * mean;
    float rstd = rsqrtf(var + 1e-5f);
    float4 gv = ((const float4*)g)[tid];
    float4 bv = ((const float4*)b)[tid];
    float o[4];
    o[0] = (v.x - mean) * rstd * gv.x + bv.x;
    o[1] = (v.y - mean) * rstd * gv.y + bv.y;
    o[2] = (v.z - mean) * rstd * gv.z + bv.z;
    o[3] = (v.w - mean) * rstd * gv.w + bv.w;
    __nv_bfloat16 h[4], l[4];
    #pragma unroll
    for (int i = 0; i < 4; i++) split_bf16(o[i], h[i], l[i]);
    size_t base = (size_t)row * DD + tid * 4;
    *(__nv_bfloat162*)(oh + base)     = __nv_bfloat162(h[0], h[1]);
    *(__nv_bfloat162*)(oh + base + 2) = __nv_bfloat162(h[2], h[3]);
    *(__nv_bfloat162*)(ol + base)     = __nv_bfloat162(l[0], l[1]);
    *(__nv_bfloat162*)(ol + base + 2) = __nv_bfloat162(l[2], l[3]);
}

// ---------------- tensor-core GEMM via mma.sync ----------------
// C[M,N] = A[M,K] @ Wt^T(+bias...) ; A,W given as bf16 hi/lo, K-major.
// 3-pass split: acc += Ahi*Bhi + Ahi*Blo + Alo*Bhi (fp32 accum).
// EPI 1: bias + scatter to (B,H,S,DH) fp32
// EPI 2: bias + residual, fp32
// EPI 3: bias + GELU -> bf16 hi/lo (Ch/Cl)
//
// block 128x128, 256 thr (8 warps: 4m x 2n, warp tile 32x64), BK=32,
// cp.async double-buffered smem, row stride 80B (conflict-free ldmatrix).
#define LDB 80            // bytes per 32-elem row in smem
#define ARR_SZ 10240      // 128 rows * 80B
#define STG_SZ 40960      // 4 arrays (Ah,Al,Bh,Bl)
template<int EPI>
__global__ void __launch_bounds__(256)
gemm_mma(const __nv_bfloat16* __restrict__ Ah, const __nv_bfloat16* __restrict__ Al,
         const __nv_bfloat16* __restrict__ Wh, const __nv_bfloat16* __restrict__ Wl,
         const float* __restrict__ bias, const float* __restrict__ res,
         float* __restrict__ C, __nv_bfloat16* __restrict__ Ch, __nv_bfloat16* __restrict__ Cl,
         int M, int N, int K)
{
    extern __shared__ char smem[];
    const uint32_t sb = smem_u32(smem);
    const int tid = threadIdx.x;
    const int wid = tid >> 5, lane = tid & 31;
    const int wm = wid & 3, wn = wid >> 2;
    const int m0 = blockIdx.y * 128, n0 = blockIdx.x * 128;

    float acc[2][8][4] = {};
    const int NK = K >> 5;

    // ---- stage loader ----
    auto load_stage = [&](int kc, int buf) {
        int k0 = kc << 5;
        uint32_t stb = sb + buf * STG_SZ;
        #pragma unroll
        for (int i = 0; i < 8; i++) {
            int c = tid + i * 256;         // 0..2047
            int arr = c >> 9;              // 0:Ah 1:Al 2:Bh 3:Bl
            int cc = c & 511;
            int row = cc >> 2, col = cc & 3;
            const __nv_bfloat16* gsrc;
            if      (arr == 0) gsrc = Ah + (size_t)(m0 + row) * K + k0 + col * 8;
            else if (arr == 1) gsrc = Al + (size_t)(m0 + row) * K + k0 + col * 8;
            else if (arr == 2) gsrc = Wh + (size_t)(n0 + row) * K + k0 + col * 8;
            else               gsrc = Wl + (size_t)(n0 + row) * K + k0 + col * 8;
            cp_async16(stb + arr * ARR_SZ + row * LDB + col * 16, gsrc);
        }
        asm volatile("cp.async.commit_group;" ::: "memory");
    };

    load_stage(0, 0);

    for (int kc = 0; kc < NK; kc++) {
        int buf = kc & 1;
        if (kc + 1 < NK) {
            load_stage(kc + 1, buf ^ 1);
            asm volatile("cp.async.wait_group 1;" ::: "memory");
        } else {
            asm volatile("cp.async.wait_group 0;" ::: "memory");
        }
        __syncthreads();

        uint32_t stb = sb + buf * STG_SZ;
        #pragma unroll
        for (int ks = 0; ks < 2; ks++) {
            uint32_t Af[2][4], Af2[2][4], Bf[8][2], Bf2[8][2];
            // A frags: rows wm*32+mt*16+(lane&15), kcol = ks*16+(lane>>4)*8
            int ar = lane & 15, ac = ks * 16 + (lane >> 4) * 8;
            #pragma unroll
            for (int mt = 0; mt < 2; mt++) {
                uint32_t a = stb + (wm * 32 + mt * 16 + ar) * LDB + ac * 2;
                ldsm_x4(Af[mt], a);
                ldsm_x4(Af2[mt], a + ARR_SZ);
            }
            // B frags: 4 ldmatrix.x4 cover 8 ntiles
            int gq = lane >> 3, l8 = lane & 7;
            int br = (gq >> 1) * 8 + l8, bc = ks * 16 + (gq & 1) * 8;
            #pragma unroll
            for (int p = 0; p < 4; p++) {
                uint32_t a = stb + 2 * ARR_SZ + (wn * 64 + p * 16 + br) * LDB + bc * 2;
                uint32_t t[4];
                ldsm_x4(t, a);
                Bf[2*p][0] = t[0]; Bf[2*p][1] = t[1];
                Bf[2*p+1][0] = t[2]; Bf[2*p+1][1] = t[3];
                ldsm_x4(t, a + ARR_SZ);
                Bf2[2*p][0] = t[0]; Bf2[2*p][1] = t[1];
                Bf2[2*p+1][0] = t[2]; Bf2[2*p+1][1] = t[3];
            }
            #pragma unroll
            for (int mt = 0; mt < 2; mt++)
                #pragma unroll
                for (int nt = 0; nt < 8; nt++) {
                    mma16816(acc[mt][nt], Af[mt],  Bf[nt]);
                    mma16816(acc[mt][nt], Af[mt],  Bf2[nt]);
                    mma16816(acc[mt][nt], Af2[mt], Bf[nt]);
                }
        }
        __syncthreads();
    }

    // ---- epilogue ----
    int rb = m0 + wm * 32 + (lane >> 2);
    int cb = n0 + wn * 64 + (lane & 3) * 2;
    #pragma unroll
    for (int mt = 0; mt < 2; mt++) {
        #pragma unroll
        for (int half = 0; half < 2; half++) {
            int r = rb + mt * 16 + half * 8;
            #pragma unroll
            for (int nt = 0; nt < 8; nt++) {
                int n = cb + nt * 8;
                float2 bv = *(const float2*)(bias + n);
                float v0 = acc[mt][nt][half * 2 + 0] + bv.x;
                float v1 = acc[mt][nt][half * 2 + 1] + bv.y;
                if (EPI == 2) {
                    float2 rv = *(const float2*)(res + (size_t)r * N + n);
                    v0 += rv.x; v1 += rv.y;
                    *(float2*)(C + (size_t)r * N + n) = make_float2(v0, v1);
                } else if (EPI == 1) {
                    int b_ = r >> 10, s = r & 1023, hh = n >> 6, dh = n & 63;
                    *(float2*)(C + (((size_t)(b_ * HH + hh) * SS + s) * DHH + dh)) = make_float2(v0, v1);
                } else if (EPI == 3) {
                    v0 = 0.5f * v0 * (1.0f + erff(v0 * 0.70710678118654752f));
                    v1 = 0.5f * v1 * (1.0f + erff(v1 * 0.70710678118654752f));
                    __nv_bfloat16 h0, l0, h1, l1;
                    split_bf16(v0, h0, l0); split_bf16(v1, h1, l1);
                    *(__nv_bfloat162*)(Ch + (size_t)r * N + n) = __nv_bfloat162(h0, h1);
                    *(__nv_bfloat162*)(Cl + (size_t)r * N + n) = __nv_bfloat162(l0, l1);
                }
            }
        }
    }
}

// ---------------- Flash attention (SIMT fp32, bf16 hi/lo output) -----------
__global__ void __launch_bounds__(256)
flash_attn(const float* __restrict__ Q, const float* __restrict__ K,
           const float* __restrict__ V,
           __nv_bfloat16* __restrict__ Oh, __nv_bfloat16* __restrict__ Ol)
{
    extern __shared__ float sm[];
    const int LD = 65;
    float* Qs = sm;
    float* Ks = Qs + 64 * LD;
    float* Vs = Ks + 64 * LD;
    float* Ps = Vs + 64 * LD;
    float* m_sh = Ps + 64 * LD;
    float* l_sh = m_sh + 64;

    int tid = threadIdx.x;
    int tx = tid & 15, ty = tid >> 4;
    int bh = blockIdx.y;
    int q0 = blockIdx.x * 64;
    const float scale = 1.0f / 32.0f;

    const float* Qb = Q + ((size_t)bh * SS + q0) * DHH;
    const float* Kb = K + (size_t)bh * SS * DHH;
    const float* Vb = V + (size_t)bh * SS * DHH;

    for (int i = tid; i < 64 * 64; i += 256) {
        int r = i >> 6, d = i & 63;
        Qs[r * LD + d] = Qb[(size_t)r * DHH + d] * scale;
    }
    int r0 = ty * 4, c0 = tx * 4;
    if (tx == 0) {
        #pragma unroll
        for (int i = 0; i < 4; i++) { m_sh[r0 + i] = -1e30f; l_sh[r0 + i] = 0.f; }
    }
    float acc[4][4] = {};
    __syncthreads();

    for (int t = 0; t < SS / 64; t++) {
        const float* Kt = Kb + (size_t)t * 64 * DHH;
        const float* Vt = Vb + (size_t)t * 64 * DHH;
        for (int i = tid; i < 64 * 64; i += 256) {
            int r = i >> 6, d = i & 63;
            Ks[r * LD + d] = Kt[i];
            Vs[r * LD + d] = Vt[i];
        }
        __syncthreads();

        float s[4][4] = {};
        #pragma unroll
        for (int d = 0; d < 64; d++) {
            float qv[4], kv[4];
            #pragma unroll
            for (int i = 0; i < 4; i++) qv[i] = Qs[(r0 + i) * LD + d];
            #pragma unroll
            for (int j = 0; j < 4; j++) kv[j] = Ks[(c0 + j) * LD + d];
            #pragma unroll
            for (int i = 0; i < 4; i++)
                #pragma unroll
                for (int j = 0; j < 4; j++)
                    s[i][j] += qv[i] * kv[j];
        }

        float rm[4], m_new[4], alpha[4], rs[4];
        #pragma unroll
        for (int i = 0; i < 4; i++)
            rm[i] = fmaxf(fmaxf(s[i][0], s[i][1]), fmaxf(s[i][2], s[i][3]));
        #pragma unroll
        for (int o = 1; o < 16; o <<= 1) {
            #pragma unroll
            for (int i = 0; i < 4; i++)
                rm[i] = fmaxf(rm[i], __shfl_xor_sync(0xffffffffu, rm[i], o));
        }
        #pragma unroll
        for (int i = 0; i < 4; i++) {
            float mo = m_sh[r0 + i];
            m_new[i] = fmaxf(mo, rm[i]);
            alpha[i] = __expf(mo - m_new[i]);
            rs[i] = 0.f;
            #pragma unroll
            for (int j = 0; j < 4; j++) {
                float p = __expf(s[i][j] - m_new[i]);
                s[i][j] = p;
                rs[i] += p;
            }
        }
        #pragma unroll
        for (int o = 1; o < 16; o <<= 1) {
            #pragma unroll
            for (int i = 0; i < 4; i++)
                rs[i] += __shfl_xor_sync(0xffffffffu, rs[i], o);
        }
        #pragma unroll
        for (int i = 0; i < 4; i++)
            #pragma unroll
            for (int j = 0; j < 4; j++)
                acc[i][j] *= alpha[i];
        __syncwarp();
        if (tx == 0) {
            #pragma unroll
            for (int i = 0; i < 4; i++) {
                l_sh[r0 + i] = l_sh[r0 + i] * alpha[i] + rs[i];
                m_sh[r0 + i] = m_new[i];
            }
        }
        #pragma unroll
        for (int i = 0; i < 4; i++)
            #pragma unroll
            for (int j = 0; j < 4; j++)
                Ps[(r0 + i) * LD + c0 + j] = s[i][j];
        __syncthreads();

        #pragma unroll
        for (int k = 0; k < 64; k++) {
            float pv[4], vv[4];
            #pragma unroll
            for (int i = 0; i < 4; i++) pv[i] = Ps[(r0 + i) * LD + k];
            #pragma unroll
            for (int j = 0; j < 4; j++) vv[j] = Vs[k * LD + c0 + j];
            #pragma unroll
            for (int i = 0; i < 4; i++)
                #pragma unroll
                for (int j = 0; j < 4; j++)
                    acc[i][j] += pv[i] * vv[j];
        }
        __syncthreads();
    }

    int bb = bh >> 4, h = bh & 15;
    #pragma unroll
    for (int i = 0; i < 4; i++) {
        float inv = 1.0f / l_sh[r0 + i];
        int srow = q0 + r0 + i;
        size_t base = ((size_t)bb * SS + srow) * DD + h * DHH + c0;
        #pragma unroll
        for (int j = 0; j < 4; j += 2) {
            float v0 = acc[i][j] * inv, v1 = acc[i][j + 1] * inv;
            __nv_bfloat16 h0, l0, h1, l1;
            split_bf16(v0, h0, l0); split_bf16(v1, h1, l1);
            *(__nv_bfloat162*)(Oh + base + j) = __nv_bfloat162(h0, h1);
            *(__nv_bfloat162*)(Ol + base + j) = __nv_bfloat162(l0, l1);
        }
    }
}

// ---------------- launch ----------------
extern "C" void kernel_launch(void* const* d_in, const int* in_sizes, int n_in,
                              void* d_out, int out_size)
{
    const float* x    = (const float*)d_in[0];
    const float* wq   = (const float*)d_in[1];
    const float* bq   = (const float*)d_in[2];
    const float* wk   = (const float*)d_in[3];
    const float* bk   = (const float*)d_in[4];
    const float* wv   = (const float*)d_in[5];
    const float* bv   = (const float*)d_in[6];
    const float* wo   = (const float*)d_in[7];
    const float* bo   = (const float*)d_in[8];
    const float* g1   = (const float*)d_in[9];
    const float* b1   = (const float*)d_in[10];
    const float* g2   = (const float*)d_in[11];
    const float* b2   = (const float*)d_in[12];
    const float* wfc1 = (const float*)d_in[13];
    const float* bfc1 = (const float*)d_in[14];
    const float* wfc2 = (const float*)d_in[15];
    const float* bfc2 = (const float*)d_in[16];
    float* out = (float*)d_out;

    float *q, *k, *v, *o1;
    cudaGetSymbolAddress((void**)&q,  g_q);
    cudaGetSymbolAddress((void**)&k,  g_k);
    cudaGetSymbolAddress((void**)&v,  g_v);
    cudaGetSymbolAddress((void**)&o1, g_o1);
    __nv_bfloat16 *xh, *xl, *mh, *ml;
    cudaGetSymbolAddress((void**)&xh, g_xh);
    cudaGetSymbolAddress((void**)&xl, g_xl);
    cudaGetSymbolAddress((void**)&mh, g_mh);
    cudaGetSymbolAddress((void**)&ml, g_ml);
    __nv_bfloat16 *wqt, *wkt, *wvt, *wot, *w1t, *w2t;
    cudaGetSymbolAddress((void**)&wqt, g_wqt);
    cudaGetSymbolAddress((void**)&wkt, g_wkt);
    cudaGetSymbolAddress((void**)&wvt, g_wvt);
    cudaGetSymbolAddress((void**)&wot, g_wot);
    cudaGetSymbolAddress((void**)&w1t, g_w1t);
    cudaGetSymbolAddress((void**)&w2t, g_w2t);
    const size_t SQ = (size_t)DD * DD;
    const size_t SF = (size_t)DD * FFN;

    const int GEMM_SMEM = 2 * STG_SZ;  // 81920
    cudaFuncSetAttribute(gemm_mma<1>, cudaFuncAttributeMaxDynamicSharedMemorySize, GEMM_SMEM);
    cudaFuncSetAttribute(gemm_mma<2>, cudaFuncAttributeMaxDynamicSharedMemorySize, GEMM_SMEM);
    cudaFuncSetAttribute(gemm_mma<3>, cudaFuncAttributeMaxDynamicSharedMemorySize, GEMM_SMEM);
    const int FLASH_SMEM = (4 * 64 * 65 + 128) * (int)sizeof(float);
    cudaFuncSetAttribute(flash_attn, cudaFuncAttributeMaxDynamicSharedMemorySize, FLASH_SMEM);

    dim3 cb(32, 8);
    wconv<<<dim3(DD / 32, DD / 32), cb>>>(wq,   wqt, wqt + SQ, DD, DD);
    wconv<<<dim3(DD / 32, DD / 32), cb>>>(wk,   wkt, wkt + SQ, DD, DD);
    wconv<<<dim3(DD / 32, DD / 32), cb>>>(wv,   wvt, wvt + SQ, DD, DD);
    wconv<<<dim3(DD / 32, DD / 32), cb>>>(wo,   wot, wot + SQ, DD, DD);
    wconv<<<dim3(FFN / 32, DD / 32), cb>>>(wfc1, w1t, w1t + SF, DD, FFN);
    wconv<<<dim3(DD / 32, FFN / 32), cb>>>(wfc2, w2t, w2t + SF, FFN, DD);

    // 1. LN1 -> bf16 hi/lo
    layernorm_bf<<<ROWS, 256>>>(x, g1, b1, xh, xl);

    // 2. QKV projections -> (B,H,S,DH) fp32
    dim3 gQKV(DD / 128, ROWS / 128);
    gemm_mma<1><<<gQKV, 256, GEMM_SMEM>>>(xh, xl, wqt, wqt + SQ, bq, nullptr, q, nullptr, nullptr, ROWS, DD, DD);
    gemm_mma<1><<<gQKV, 256, GEMM_SMEM>>>(xh, xl, wkt, wkt + SQ, bk, nullptr, k, nullptr, nullptr, ROWS, DD, DD);
    gemm_mma<1><<<gQKV, 256, GEMM_SMEM>>>(xh, xl, wvt, wvt + SQ, bv, nullptr, v, nullptr, nullptr, ROWS, DD, DD);

    // 3. attention -> bf16 hi/lo (reuse xh/xl)
    flash_attn<<<dim3(SS / 64, BB * HH), 256, FLASH_SMEM>>>(q, k, v, xh, xl);

    // 4. output projection + residual(x) -> o1 fp32
    gemm_mma<2><<<gQKV, 256, GEMM_SMEM>>>(xh, xl, wot, wot + SQ, bo, x, o1, nullptr, nullptr, ROWS, DD, DD);

    // 5. LN2 -> bf16 hi/lo
    layernorm_bf<<<ROWS, 256>>>(o1, g2, b2, xh, xl);

    // 6. FC1 + GELU -> bf16 hi/lo mid
    dim3 gFC1(FFN / 128, ROWS / 128);
    gemm_mma<3><<<gFC1, 256, GEMM_SMEM>>>(xh, xl, w1t, w1t + SF, bfc1, nullptr, nullptr, mh, ml, ROWS, FFN, DD);

    // 7. FC2 + residual(o1) -> out
    dim3 gFC2(DD / 128, ROWS / 128);
    gemm_mma<2><<<gFC2, 256, GEMM_SMEM>>>(mh, ml, w2t, w2t + SF, bfc2, o1, out, nullptr, nullptr, ROWS, DD, FFN);
}

// round 4
// speedup vs baseline: 2.4105x; 1.2361x over previous
#include <cuda_runtime.h>
#include <cuda_bf16.h>
#include <math.h>
#include <stdint.h>

// ---------------- problem constants ----------------
#define BB 4
#define SS 1024
#define DD 1024
#define HH 16
#define DHH 64
#define FFN 4096
#define ROWS (BB*SS)   // 4096

// ---------------- device scratch ----------------
__device__ float g_o1 [ROWS*DD];
// activation bf16 hi/lo (LN out / attn out reuse; FFN mid separate)
__device__ __nv_bfloat16 g_xh[ROWS*DD];
__device__ __nv_bfloat16 g_xl[ROWS*DD];
__device__ __nv_bfloat16 g_mh[(size_t)ROWS*FFN];
__device__ __nv_bfloat16 g_ml[(size_t)ROWS*FFN];
// QKV in (B,H,S,DH) bf16 hi/lo
__device__ __nv_bfloat16 g_qh[ROWS*DD];
__device__ __nv_bfloat16 g_ql[ROWS*DD];
__device__ __nv_bfloat16 g_kh[ROWS*DD];
__device__ __nv_bfloat16 g_kl[ROWS*DD];
__device__ __nv_bfloat16 g_vh[ROWS*DD];
__device__ __nv_bfloat16 g_vl[ROWS*DD];
// transposed bf16 weights: [0]=hi, [1]=lo, layout [N,K] K-major
__device__ __nv_bfloat16 g_wqt[2][DD*DD];
__device__ __nv_bfloat16 g_wkt[2][DD*DD];
__device__ __nv_bfloat16 g_wvt[2][DD*DD];
__device__ __nv_bfloat16 g_wot[2][DD*DD];
__device__ __nv_bfloat16 g_w1t[2][(size_t)DD*FFN];
__device__ __nv_bfloat16 g_w2t[2][(size_t)DD*FFN];

// ---------------- small helpers ----------------
__device__ __forceinline__ uint32_t smem_u32(const void* p) {
    uint32_t a;
    asm("{ .reg .u64 t; cvta.to.shared.u64 t, %1; cvt.u32.u64 %0, t; }" : "=r"(a) : "l"(p));
    return a;
}
__device__ __forceinline__ void cp_async16(uint32_t s, const void* g) {
    asm volatile("cp.async.cg.shared.global [%0], [%1], 16;" :: "r"(s), "l"(g));
}
__device__ __forceinline__ void ldsm_x4(uint32_t* r, uint32_t addr) {
    asm volatile("ldmatrix.sync.aligned.m8n8.x4.shared.b16 {%0,%1,%2,%3}, [%4];"
        : "=r"(r[0]), "=r"(r[1]), "=r"(r[2]), "=r"(r[3]) : "r"(addr));
}
__device__ __forceinline__ void ldsm_x4_t(uint32_t* r, uint32_t addr) {
    asm volatile("ldmatrix.sync.aligned.m8n8.x4.trans.shared.b16 {%0,%1,%2,%3}, [%4];"
        : "=r"(r[0]), "=r"(r[1]), "=r"(r[2]), "=r"(r[3]) : "r"(addr));
}
__device__ __forceinline__ void mma16816(float* d, const uint32_t* a, const uint32_t* b) {
    asm volatile("mma.sync.aligned.m16n8k16.row.col.f32.bf16.bf16.f32 "
        "{%0,%1,%2,%3}, {%4,%5,%6,%7}, {%8,%9}, {%0,%1,%2,%3};"
        : "+f"(d[0]), "+f"(d[1]), "+f"(d[2]), "+f"(d[3])
        : "r"(a[0]), "r"(a[1]), "r"(a[2]), "r"(a[3]), "r"(b[0]), "r"(b[1]));
}
__device__ __forceinline__ void split_bf16(float v, __nv_bfloat16& h, __nv_bfloat16& l) {
    h = __float2bfloat16_rn(v);
    l = __float2bfloat16_rn(v - __bfloat162float(h));
}
__device__ __forceinline__ uint32_t pack_bf(__nv_bfloat16 a, __nv_bfloat16 b) {
    return (uint32_t)__bfloat16_as_ushort(a) | ((uint32_t)__bfloat16_as_ushort(b) << 16);
}

// ---------------- weight convert + transpose ----------------
__global__ void wconv(const float* __restrict__ W, __nv_bfloat16* __restrict__ Th,
                      __nv_bfloat16* __restrict__ Tl, int K, int N)
{
    __shared__ float tile[32][33];
    int tx = threadIdx.x, ty = threadIdx.y;      // 32 x 8
    int n0 = blockIdx.x * 32, k0 = blockIdx.y * 32;
    #pragma unroll
    for (int i = 0; i < 4; i++)
        tile[ty + i*8][tx] = W[(size_t)(k0 + ty + i*8) * N + n0 + tx];
    __syncthreads();
    #pragma unroll
    for (int i = 0; i < 4; i++) {
        int n = n0 + ty + i*8;
        int k = k0 + tx;
        float v = tile[tx][ty + i*8];
        __nv_bfloat16 h, l; split_bf16(v, h, l);
        Th[(size_t)n * K + k] = h;
        Tl[(size_t)n * K + k] = l;
    }
}

// ---------------- LayerNorm -> bf16 hi/lo ----------------
__global__ void layernorm_bf(const float* __restrict__ x, const float* __restrict__ g,
                             const float* __restrict__ b,
                             __nv_bfloat16* __restrict__ oh, __nv_bfloat16* __restrict__ ol)
{
    __shared__ float red0[8], red1[8];
    int row = blockIdx.x, tid = threadIdx.x;
    const float4* xr = (const float4*)(x + (size_t)row * DD);
    float4 v = xr[tid];
    float s  = v.x + v.y + v.z + v.w;
    float s2 = v.x*v.x + v.y*v.y + v.z*v.z + v.w*v.w;
    #pragma unroll
    for (int o = 16; o; o >>= 1) {
        s  += __shfl_xor_sync(0xffffffffu, s,  o);
        s2 += __shfl_xor_sync(0xffffffffu, s2, o);
    }
    if ((tid & 31) == 0) { red0[tid >> 5] = s; red1[tid >> 5] = s2; }
    __syncthreads();
    float S = 0.f, S2 = 0.f;
    #pragma unroll
    for (int i = 0; i < 8; i++) { S += red0[i]; S2 += red1[i]; }
    float mean = S * (1.f / DD);
    float var  = S2 * (1.f / DD) - mean * mean;
    float rstd = rsqrtf(var + 1e-5f);
    float4 gv = ((const float4*)g)[tid];
    float4 bv = ((const float4*)b)[tid];
    float o[4];
    o[0] = (v.x - mean) * rstd * gv.x + bv.x;
    o[1] = (v.y - mean) * rstd * gv.y + bv.y;
    o[2] = (v.z - mean) * rstd * gv.z + bv.z;
    o[3] = (v.w - mean) * rstd * gv.w + bv.w;
    __nv_bfloat16 h[4], l[4];
    #pragma unroll
    for (int i = 0; i < 4; i++) split_bf16(o[i], h[i], l[i]);
    size_t base = (size_t)row * DD + tid * 4;
    *(__nv_bfloat162*)(oh + base)     = __nv_bfloat162(h[0], h[1]);
    *(__nv_bfloat162*)(oh + base + 2) = __nv_bfloat162(h[2], h[3]);
    *(__nv_bfloat162*)(ol + base)     = __nv_bfloat162(l[0], l[1]);
    *(__nv_bfloat162*)(ol + base + 2) = __nv_bfloat162(l[2], l[3]);
}

// ---------------- tensor-core GEMM via mma.sync ----------------
// EPI 2: bias + residual -> fp32 C
// EPI 3: bias + GELU -> bf16 hi/lo (Ch/Cl) [B*S, N]
// EPI 4: (bias + val) * scl -> bf16 hi/lo scattered to (B,H,S,DH)
#define LDB 80
#define ARR_SZ 10240
#define STG_SZ 40960
template<int EPI>
__global__ void __launch_bounds__(256)
gemm_mma(const __nv_bfloat16* __restrict__ Ah, const __nv_bfloat16* __restrict__ Al,
         const __nv_bfloat16* __restrict__ Wh, const __nv_bfloat16* __restrict__ Wl,
         const float* __restrict__ bias, const float* __restrict__ res,
         float* __restrict__ C, __nv_bfloat16* __restrict__ Ch, __nv_bfloat16* __restrict__ Cl,
         int M, int N, int K, float scl)
{
    extern __shared__ char smem[];
    const uint32_t sb = smem_u32(smem);
    const int tid = threadIdx.x;
    const int wid = tid >> 5, lane = tid & 31;
    const int wm = wid & 3, wn = wid >> 2;
    const int m0 = blockIdx.y * 128, n0 = blockIdx.x * 128;

    float acc[2][8][4] = {};
    const int NK = K >> 5;

    auto load_stage = [&](int kc, int buf) {
        int k0 = kc << 5;
        uint32_t stb = sb + buf * STG_SZ;
        #pragma unroll
        for (int i = 0; i < 8; i++) {
            int c = tid + i * 256;
            int arr = c >> 9;
            int cc = c & 511;
            int row = cc >> 2, col = cc & 3;
            const __nv_bfloat16* gsrc;
            if      (arr == 0) gsrc = Ah + (size_t)(m0 + row) * K + k0 + col * 8;
            else if (arr == 1) gsrc = Al + (size_t)(m0 + row) * K + k0 + col * 8;
            else if (arr == 2) gsrc = Wh + (size_t)(n0 + row) * K + k0 + col * 8;
            else               gsrc = Wl + (size_t)(n0 + row) * K + k0 + col * 8;
            cp_async16(stb + arr * ARR_SZ + row * LDB + col * 16, gsrc);
        }
        asm volatile("cp.async.commit_group;" ::: "memory");
    };

    load_stage(0, 0);

    for (int kc = 0; kc < NK; kc++) {
        int buf = kc & 1;
        if (kc + 1 < NK) {
            load_stage(kc + 1, buf ^ 1);
            asm volatile("cp.async.wait_group 1;" ::: "memory");
        } else {
            asm volatile("cp.async.wait_group 0;" ::: "memory");
        }
        __syncthreads();

        uint32_t stb = sb + buf * STG_SZ;
        #pragma unroll
        for (int ks = 0; ks < 2; ks++) {
            uint32_t Af[2][4], Af2[2][4], Bf[8][2], Bf2[8][2];
            int ar = lane & 15, ac = ks * 16 + (lane >> 4) * 8;
            #pragma unroll
            for (int mt = 0; mt < 2; mt++) {
                uint32_t a = stb + (wm * 32 + mt * 16 + ar) * LDB + ac * 2;
                ldsm_x4(Af[mt], a);
                ldsm_x4(Af2[mt], a + ARR_SZ);
            }
            int gq = lane >> 3, l8 = lane & 7;
            int br = (gq >> 1) * 8 + l8, bc = ks * 16 + (gq & 1) * 8;
            #pragma unroll
            for (int p = 0; p < 4; p++) {
                uint32_t a = stb + 2 * ARR_SZ + (wn * 64 + p * 16 + br) * LDB + bc * 2;
                uint32_t t[4];
                ldsm_x4(t, a);
                Bf[2*p][0] = t[0]; Bf[2*p][1] = t[1];
                Bf[2*p+1][0] = t[2]; Bf[2*p+1][1] = t[3];
                ldsm_x4(t, a + ARR_SZ);
                Bf2[2*p][0] = t[0]; Bf2[2*p][1] = t[1];
                Bf2[2*p+1][0] = t[2]; Bf2[2*p+1][1] = t[3];
            }
            #pragma unroll
            for (int mt = 0; mt < 2; mt++)
                #pragma unroll
                for (int nt = 0; nt < 8; nt++) {
                    mma16816(acc[mt][nt], Af[mt],  Bf[nt]);
                    mma16816(acc[mt][nt], Af[mt],  Bf2[nt]);
                    mma16816(acc[mt][nt], Af2[mt], Bf[nt]);
                }
        }
        __syncthreads();
    }

    // ---- epilogue ----
    int rb = m0 + wm * 32 + (lane >> 2);
    int cb = n0 + wn * 64 + (lane & 3) * 2;
    #pragma unroll
    for (int mt = 0; mt < 2; mt++) {
        #pragma unroll
        for (int half = 0; half < 2; half++) {
            int r = rb + mt * 16 + half * 8;
            #pragma unroll
            for (int nt = 0; nt < 8; nt++) {
                int n = cb + nt * 8;
                float2 bv = *(const float2*)(bias + n);
                float v0 = acc[mt][nt][half * 2 + 0] + bv.x;
                float v1 = acc[mt][nt][half * 2 + 1] + bv.y;
                if (EPI == 2) {
                    float2 rv = *(const float2*)(res + (size_t)r * N + n);
                    v0 += rv.x; v1 += rv.y;
                    *(float2*)(C + (size_t)r * N + n) = make_float2(v0, v1);
                } else if (EPI == 3) {
                    v0 = 0.5f * v0 * (1.0f + erff(v0 * 0.70710678118654752f));
                    v1 = 0.5f * v1 * (1.0f + erff(v1 * 0.70710678118654752f));
                    __nv_bfloat16 h0, l0, h1, l1;
                    split_bf16(v0, h0, l0); split_bf16(v1, h1, l1);
                    *(__nv_bfloat162*)(Ch + (size_t)r * N + n) = __nv_bfloat162(h0, h1);
                    *(__nv_bfloat162*)(Cl + (size_t)r * N + n) = __nv_bfloat162(l0, l1);
                } else if (EPI == 4) {
                    v0 *= scl; v1 *= scl;
                    __nv_bfloat16 h0, l0, h1, l1;
                    split_bf16(v0, h0, l0); split_bf16(v1, h1, l1);
                    int b_ = r >> 10, s = r & 1023, hh = n >> 6, dh = n & 63;
                    size_t off = ((size_t)(b_ * HH + hh) * SS + s) * DHH + dh;
                    *(__nv_bfloat162*)(Ch + off) = __nv_bfloat162(h0, h1);
                    *(__nv_bfloat162*)(Cl + off) = __nv_bfloat162(l0, l1);
                }
            }
        }
    }
}

// ---------------- Flash attention via mma.sync ----------------
// BQ=128, BK=64, DH=64; 8 warps, each owns 16 Q rows.
// S = Qh*Kh + Qh*Kl + Ql*Kh ; O += Ph*Vh + Ph*Vl + Pl*Vh (all fp32 accum).
#define LDK 144
#define FQ_SZ 18432           // 128 rows * 144
#define FST0  36864
#define FST_SZ 36864          // per stage: Kh,Kl,Vh,Vl each 9216
#define FARR  9216
#define FLASH_SMEM (FST0 + 2*FST_SZ)   // 110592
__global__ void __launch_bounds__(256)
flash_mma(const __nv_bfloat16* __restrict__ Qh_, const __nv_bfloat16* __restrict__ Ql_,
          const __nv_bfloat16* __restrict__ Kh_, const __nv_bfloat16* __restrict__ Kl_,
          const __nv_bfloat16* __restrict__ Vh_, const __nv_bfloat16* __restrict__ Vl_,
          __nv_bfloat16* __restrict__ Oh, __nv_bfloat16* __restrict__ Ol)
{
    extern __shared__ char smc[];
    const uint32_t sb = smem_u32(smc);
    int tid = threadIdx.x, lane = tid & 31, w = tid >> 5;
    int bh = blockIdx.y, q0 = blockIdx.x * 128;
    size_t qbase = ((size_t)bh * SS + q0) * DHH;
    size_t kvbase = (size_t)bh * SS * DHH;

    // Q hi/lo -> smem
    #pragma unroll
    for (int i = 0; i < 8; i++) {
        int c = tid + i * 256;        // 0..2047
        int arr = c >> 10, cc = c & 1023;
        int row = cc >> 3, col = cc & 7;
        const __nv_bfloat16* src = (arr ? Ql_ : Qh_) + qbase + row * 64 + col * 8;
        cp_async16(sb + arr * FQ_SZ + row * LDK + col * 16, src);
    }
    auto load_stage = [&](int t, int buf) {
        size_t base = kvbase + (size_t)t * 64 * DHH;
        #pragma unroll
        for (int i = 0; i < 8; i++) {
            int c = tid + i * 256;
            int arr = c >> 9, cc = c & 511;
            int row = cc >> 3, col = cc & 7;
            const __nv_bfloat16* src;
            if      (arr == 0) src = Kh_;
            else if (arr == 1) src = Kl_;
            else if (arr == 2) src = Vh_;
            else               src = Vl_;
            src += base + row * 64 + col * 8;
            cp_async16(sb + FST0 + buf * FST_SZ + arr * FARR + row * LDK + col * 16, src);
        }
    };
    load_stage(0, 0);
    asm volatile("cp.async.commit_group;" ::: "memory");

    uint32_t qh[4][4], ql[4][4];
    float m2[2] = {-1e30f, -1e30f}, l2[2] = {0.f, 0.f};
    float acc_o[8][4] = {};

    for (int t = 0; t < SS / 64; t++) {
        int buf = t & 1;
        if (t + 1 < SS / 64) {
            load_stage(t + 1, (t + 1) & 1);
            asm volatile("cp.async.commit_group;" ::: "memory");
            asm volatile("cp.async.wait_group 1;" ::: "memory");
        } else {
            asm volatile("cp.async.wait_group 0;" ::: "memory");
        }
        __syncthreads();
        if (t == 0) {
            #pragma unroll
            for (int ks = 0; ks < 4; ks++) {
                uint32_t a = sb + (w * 16 + (lane & 15)) * LDK + ks * 32 + (lane >> 4) * 16;
                ldsm_x4(qh[ks], a);
                ldsm_x4(ql[ks], a + FQ_SZ);
            }
        }
        uint32_t stb = sb + FST0 + buf * FST_SZ;

        // ---- S = Q K^T ----
        float s[8][4] = {};
        int gq = lane >> 3, l8 = lane & 7;
        int br = (gq >> 1) * 8 + l8;
        #pragma unroll
        for (int ks = 0; ks < 4; ks++) {
            uint32_t Bh[8][2], Bl[8][2];
            int bcB = ks * 32 + (gq & 1) * 16;
            #pragma unroll
            for (int p = 0; p < 4; p++) {
                uint32_t a = stb + (p * 16 + br) * LDK + bcB;
                uint32_t t4[4];
                ldsm_x4(t4, a);
                Bh[2*p][0] = t4[0]; Bh[2*p][1] = t4[1];
                Bh[2*p+1][0] = t4[2]; Bh[2*p+1][1] = t4[3];
                ldsm_x4(t4, a + FARR);
                Bl[2*p][0] = t4[0]; Bl[2*p][1] = t4[1];
                Bl[2*p+1][0] = t4[2]; Bl[2*p+1][1] = t4[3];
            }
            #pragma unroll
            for (int nt = 0; nt < 8; nt++) {
                mma16816(s[nt], qh[ks], Bh[nt]);
                mma16816(s[nt], qh[ks], Bl[nt]);
                mma16816(s[nt], ql[ks], Bh[nt]);
            }
        }

        // ---- online softmax (rows: lane/4 and lane/4+8 within warp tile) ----
        float rm0 = -1e30f, rm1 = -1e30f;
        #pragma unroll
        for (int nt = 0; nt < 8; nt++) {
            rm0 = fmaxf(rm0, fmaxf(s[nt][0], s[nt][1]));
            rm1 = fmaxf(rm1, fmaxf(s[nt][2], s[nt][3]));
        }
        rm0 = fmaxf(rm0, __shfl_xor_sync(0xffffffffu, rm0, 1));
        rm0 = fmaxf(rm0, __shfl_xor_sync(0xffffffffu, rm0, 2));
        rm1 = fmaxf(rm1, __shfl_xor_sync(0xffffffffu, rm1, 1));
        rm1 = fmaxf(rm1, __shfl_xor_sync(0xffffffffu, rm1, 2));
        float mn0 = fmaxf(m2[0], rm0), mn1 = fmaxf(m2[1], rm1);
        float al0 = __expf(m2[0] - mn0), al1 = __expf(m2[1] - mn1);
        float rs0 = 0.f, rs1 = 0.f;
        #pragma unroll
        for (int nt = 0; nt < 8; nt++) {
            s[nt][0] = __expf(s[nt][0] - mn0);
            s[nt][1] = __expf(s[nt][1] - mn0);
            s[nt][2] = __expf(s[nt][2] - mn1);
            s[nt][3] = __expf(s[nt][3] - mn1);
            rs0 += s[nt][0] + s[nt][1];
            rs1 += s[nt][2] + s[nt][3];
        }
        rs0 += __shfl_xor_sync(0xffffffffu, rs0, 1);
        rs0 += __shfl_xor_sync(0xffffffffu, rs0, 2);
        rs1 += __shfl_xor_sync(0xffffffffu, rs1, 1);
        rs1 += __shfl_xor_sync(0xffffffffu, rs1, 2);
        l2[0] = l2[0] * al0 + rs0;
        l2[1] = l2[1] * al1 + rs1;
        m2[0] = mn0; m2[1] = mn1;
        #pragma unroll
        for (int nt = 0; nt < 8; nt++) {
            acc_o[nt][0] *= al0; acc_o[nt][1] *= al0;
            acc_o[nt][2] *= al1; acc_o[nt][3] *= al1;
        }

        // ---- O += P V ----
        int vr = ((lane >> 3) & 1) * 8 + (lane & 7);
        int vcb = ((lane >> 4) * 8) * 2;
        #pragma unroll
        for (int ks = 0; ks < 4; ks++) {
            // P fragments (A operand) from score regs: ntiles 2ks, 2ks+1
            uint32_t ph[4], pl[4];
            #pragma unroll
            for (int q2 = 0; q2 < 2; q2++) {
                float p0 = s[2*ks + q2][0], p1 = s[2*ks + q2][1];
                float p2 = s[2*ks + q2][2], p3 = s[2*ks + q2][3];
                __nv_bfloat16 h0,lo0,h1,lo1,h2,lo2,h3,lo3;
                split_bf16(p0, h0, lo0); split_bf16(p1, h1, lo1);
                split_bf16(p2, h2, lo2); split_bf16(p3, h3, lo3);
                ph[2*q2]     = pack_bf(h0, h1);  pl[2*q2]     = pack_bf(lo0, lo1);
                ph[2*q2 + 1] = pack_bf(h2, h3);  pl[2*q2 + 1] = pack_bf(lo2, lo3);
            }
            // V fragments (B operand) via trans ldmatrix
            uint32_t Vh[8][2], Vl[8][2];
            #pragma unroll
            for (int np = 0; np < 4; np++) {
                uint32_t a = stb + 2 * FARR + (ks * 16 + vr) * LDK + np * 32 + vcb;
                uint32_t t4[4];
                ldsm_x4_t(t4, a);
                Vh[2*np][0] = t4[0]; Vh[2*np][1] = t4[1];
                Vh[2*np+1][0] = t4[2]; Vh[2*np+1][1] = t4[3];
                ldsm_x4_t(t4, a + FARR);
                Vl[2*np][0] = t4[0]; Vl[2*np][1] = t4[1];
                Vl[2*np+1][0] = t4[2]; Vl[2*np+1][1] = t4[3];
            }
            #pragma unroll
            for (int nt = 0; nt < 8; nt++) {
                mma16816(acc_o[nt], ph, Vh[nt]);
                mma16816(acc_o[nt], ph, Vl[nt]);
                mma16816(acc_o[nt], pl, Vh[nt]);
            }
        }
        __syncthreads();
    }

    // ---- epilogue: O/l -> bf16 hi/lo, (B,S,D) layout ----
    float inv0 = 1.0f / l2[0], inv1 = 1.0f / l2[1];
    int g = lane >> 2;
    int bb = bh >> 4, hh = bh & 15;
    int r_lo = q0 + w * 16 + g, r_hi = r_lo + 8;
    int cbase = hh * 64 + (lane & 3) * 2;
    #pragma unroll
    for (int nt = 0; nt < 8; nt++) {
        int cc = cbase + nt * 8;
        float v0 = acc_o[nt][0] * inv0, v1 = acc_o[nt][1] * inv0;
        float v2 = acc_o[nt][2] * inv1, v3 = acc_o[nt][3] * inv1;
        __nv_bfloat16 h0,lo0,h1,lo1,h2,lo2,h3,lo3;
        split_bf16(v0, h0, lo0); split_bf16(v1, h1, lo1);
        split_bf16(v2, h2, lo2); split_bf16(v3, h3, lo3);
        size_t off_lo = ((size_t)bb * SS + r_lo) * DD + cc;
        size_t off_hi = ((size_t)bb * SS + r_hi) * DD + cc;
        *(__nv_bfloat162*)(Oh + off_lo) = __nv_bfloat162(h0, h1);
        *(__nv_bfloat162*)(Ol + off_lo) = __nv_bfloat162(lo0, lo1);
        *(__nv_bfloat162*)(Oh + off_hi) = __nv_bfloat162(h2, h3);
        *(__nv_bfloat162*)(Ol + off_hi) = __nv_bfloat162(lo2, lo3);
    }
}

// ---------------- launch ----------------
extern "C" void kernel_launch(void* const* d_in, const int* in_sizes, int n_in,
                              void* d_out, int out_size)
{
    const float* x    = (const float*)d_in[0];
    const float* wq   = (const float*)d_in[1];
    const float* bq   = (const float*)d_in[2];
    const float* wk   = (const float*)d_in[3];
    const float* bk   = (const float*)d_in[4];
    const float* wv   = (const float*)d_in[5];
    const float* bv   = (const float*)d_in[6];
    const float* wo   = (const float*)d_in[7];
    const float* bo   = (const float*)d_in[8];
    const float* g1   = (const float*)d_in[9];
    const float* b1   = (const float*)d_in[10];
    const float* g2   = (const float*)d_in[11];
    const float* b2   = (const float*)d_in[12];
    const float* wfc1 = (const float*)d_in[13];
    const float* bfc1 = (const float*)d_in[14];
    const float* wfc2 = (const float*)d_in[15];
    const float* bfc2 = (const float*)d_in[16];
    float* out = (float*)d_out;

    float *o1;
    cudaGetSymbolAddress((void**)&o1, g_o1);
    __nv_bfloat16 *xh, *xl, *mh, *ml, *qh, *qlp, *kh, *kl, *vh, *vl;
    cudaGetSymbolAddress((void**)&xh, g_xh);
    cudaGetSymbolAddress((void**)&xl, g_xl);
    cudaGetSymbolAddress((void**)&mh, g_mh);
    cudaGetSymbolAddress((void**)&ml, g_ml);
    cudaGetSymbolAddress((void**)&qh, g_qh);
    cudaGetSymbolAddress((void**)&qlp, g_ql);
    cudaGetSymbolAddress((void**)&kh, g_kh);
    cudaGetSymbolAddress((void**)&kl, g_kl);
    cudaGetSymbolAddress((void**)&vh, g_vh);
    cudaGetSymbolAddress((void**)&vl, g_vl);
    __nv_bfloat16 *wqt, *wkt, *wvt, *wot, *w1t, *w2t;
    cudaGetSymbolAddress((void**)&wqt, g_wqt);
    cudaGetSymbolAddress((void**)&wkt, g_wkt);
    cudaGetSymbolAddress((void**)&wvt, g_wvt);
    cudaGetSymbolAddress((void**)&wot, g_wot);
    cudaGetSymbolAddress((void**)&w1t, g_w1t);
    cudaGetSymbolAddress((void**)&w2t, g_w2t);
    const size_t SQ = (size_t)DD * DD;
    const size_t SF = (size_t)DD * FFN;

    const int GEMM_SMEM = 2 * STG_SZ;  // 81920
    cudaFuncSetAttribute(gemm_mma<2>, cudaFuncAttributeMaxDynamicSharedMemorySize, GEMM_SMEM);
    cudaFuncSetAttribute(gemm_mma<3>, cudaFuncAttributeMaxDynamicSharedMemorySize, GEMM_SMEM);
    cudaFuncSetAttribute(gemm_mma<4>, cudaFuncAttributeMaxDynamicSharedMemorySize, GEMM_SMEM);
    cudaFuncSetAttribute(flash_mma, cudaFuncAttributeMaxDynamicSharedMemorySize, FLASH_SMEM);

    dim3 cb(32, 8);
    wconv<<<dim3(DD / 32, DD / 32), cb>>>(wq,   wqt, wqt + SQ, DD, DD);
    wconv<<<dim3(DD / 32, DD / 32), cb>>>(wk,   wkt, wkt + SQ, DD, DD);
    wconv<<<dim3(DD / 32, DD / 32), cb>>>(wv,   wvt, wvt + SQ, DD, DD);
    wconv<<<dim3(DD / 32, DD / 32), cb>>>(wo,   wot, wot + SQ, DD, DD);
    wconv<<<dim3(FFN / 32, DD / 32), cb>>>(wfc1, w1t, w1t + SF, DD, FFN);
    wconv<<<dim3(DD / 32, FFN / 32), cb>>>(wfc2, w2t, w2t + SF, FFN, DD);

    // 1. LN1 -> bf16 hi/lo
    layernorm_bf<<<ROWS, 256>>>(x, g1, b1, xh, xl);

    // 2. QKV projections -> (B,H,S,DH) bf16 hi/lo (Q pre-scaled by 1/32)
    dim3 gQKV(DD / 128, ROWS / 128);
    gemm_mma<4><<<gQKV, 256, GEMM_SMEM>>>(xh, xl, wqt, wqt + SQ, bq, nullptr, nullptr, qh, qlp, ROWS, DD, DD, 1.0f / 32.0f);
    gemm_mma<4><<<gQKV, 256, GEMM_SMEM>>>(xh, xl, wkt, wkt + SQ, bk, nullptr, nullptr, kh, kl,  ROWS, DD, DD, 1.0f);
    gemm_mma<4><<<gQKV, 256, GEMM_SMEM>>>(xh, xl, wvt, wvt + SQ, bv, nullptr, nullptr, vh, vl,  ROWS, DD, DD, 1.0f);

    // 3. attention -> bf16 hi/lo (B,S,D) into xh/xl
    flash_mma<<<dim3(SS / 128, BB * HH), 256, FLASH_SMEM>>>(qh, qlp, kh, kl, vh, vl, xh, xl);

    // 4. output projection + residual(x) -> o1 fp32
    gemm_mma<2><<<gQKV, 256, GEMM_SMEM>>>(xh, xl, wot, wot + SQ, bo, x, o1, nullptr, nullptr, ROWS, DD, DD, 1.0f);

    // 5. LN2 -> bf16 hi/lo
    layernorm_bf<<<ROWS, 256>>>(o1, g2, b2, xh, xl);

    // 6. FC1 + GELU -> bf16 hi/lo mid
    dim3 gFC1(FFN / 128, ROWS / 128);
    gemm_mma<3><<<gFC1, 256, GEMM_SMEM>>>(xh, xl, w1t, w1t + SF, bfc1, nullptr, nullptr, mh, ml, ROWS, FFN, DD, 1.0f);

    // 7. FC2 + residual(o1) -> out
    dim3 gFC2(DD / 128, ROWS / 128);
    gemm_mma<2><<<gFC2, 256, GEMM_SMEM>>>(mh, ml, w2t, w2t + SF, bfc2, o1, out, nullptr, nullptr, ROWS, DD, FFN, 1.0f);
}